// round 2
// baseline (speedup 1.0000x reference)
#include <cuda_runtime.h>

#define GRID 128
#define NTH  256
#define B    256
#define T    512

// ---------------- persistent device state (allocation-free scratch) ----------
__device__ float g_obsim[64][B];        // ob_sim, [o][b]
__device__ float g_h0[2][128][B];       // double-buffered masked h0
__device__ float g_h1[2][128][B];       // double-buffered masked h1
__device__ float g_xt[138][B];          // x concat: [0:64)=ob_t, [64:128)=next_ob_sim, [128:138)=ac_t
__device__ float g_t1[256][B];          // transition hidden
__device__ float g_nh0[128][B];         // raw (unmasked) nh0 for GRU1 input
__device__ float g_hdec[256][B];        // decoder hidden
__device__ unsigned g_bar_count;        // monotonic across launches
__device__ unsigned g_bar_gen;          // monotonic across launches

__device__ __forceinline__ float sigmoidf_(float x){ return 1.0f/(1.0f + expf(-x)); }

__device__ __forceinline__ void grid_barrier(unsigned target){
    __syncthreads();
    if (threadIdx.x == 0){
        __threadfence();
        unsigned old = atomicAdd(&g_bar_count, 1u);
        if (old == target * GRID - 1u){
            asm volatile("st.release.gpu.u32 [%0], %1;" :: "l"(&g_bar_gen), "r"(target) : "memory");
        } else {
            unsigned v;
            do {
                asm volatile("ld.acquire.gpu.u32 %0, [%1];" : "=r"(v) : "l"(&g_bar_gen) : "memory");
            } while ((int)(v - target) < 0);
        }
    }
    __syncthreads();
}

__global__ void __launch_bounds__(NTH, 1) rnn_kernel(
    const float* __restrict__ ob,   const float* __restrict__ acg,  const float* __restrict__ noise,
    const float* __restrict__ prev, const int*   __restrict__ seql,
    const float* __restrict__ Wih0, const float* __restrict__ Whh0, const float* __restrict__ bih0, const float* __restrict__ bhh0,
    const float* __restrict__ Wih1, const float* __restrict__ Whh1, const float* __restrict__ bih1, const float* __restrict__ bhh1,
    const float* __restrict__ Wt1,  const float* __restrict__ bt1,  const float* __restrict__ Wt2,  const float* __restrict__ bt2,
    const float* __restrict__ Wd1,  const float* __restrict__ bd1,
    const float* __restrict__ Wmu,  const float* __restrict__ bmu,  const float* __restrict__ Wstd, const float* __restrict__ bstd,
    float* __restrict__ out)
{
    const int cta = blockIdx.x;
    const int tid = threadIdx.x;
    const int gt  = cta * NTH + tid;

    // ---- per-CTA static weight slices in SMEM ----
    __shared__ float s_wt1[2][74];          // trans1 cols (j0, j0+1)
    __shared__ float s_wt2[256];            // trans2 col o6
    __shared__ float s_wih0[3][138];        // GRU0 rows i, i+128, i+256
    __shared__ float s_whh0[3][128];
    __shared__ float s_wih1[3][128];        // GRU1
    __shared__ float s_whh1[3][128];
    __shared__ float s_wd1[2][266];         // dec1 cols (j0, j0+1), rows reordered to [h1 | g_xt order]
    __shared__ float s_wmu[256], s_wstd[256];
    __shared__ float s_b[20];
    __shared__ int   s_seq[B];
    __shared__ unsigned s_base;

    const int j0  = 2 * cta;                // S1/S5 neuron pair
    const int o6  = cta >> 1;               // S2/S6 neuron
    const int half = cta & 1;               // batch half for S2/S6

    if (tid == 0) s_base = *((volatile unsigned*)&g_bar_gen);

    for (int e = tid; e < 2*74; e += NTH){ int j=e/74, k=e%74; s_wt1[j][k] = Wt1[k*256 + j0 + j]; }
    for (int e = tid; e < 256;  e += NTH) s_wt2[e] = Wt2[e*64 + o6];
    for (int e = tid; e < 3*138; e += NTH){ int g=e/138, k=e%138; s_wih0[g][k] = Wih0[(cta + g*128)*138 + k]; }
    for (int e = tid; e < 3*128; e += NTH){
        int g=e/128, k=e%128;
        s_whh0[g][k] = Whh0[(cta + g*128)*128 + k];
        s_wih1[g][k] = Wih1[(cta + g*128)*128 + k];
        s_whh1[g][k] = Whh1[(cta + g*128)*128 + k];
    }
    for (int e = tid; e < 2*266; e += NTH){
        int j=e/266, k=e%266, row;
        if (k < 128) row = k;                                   // h1 (out) part: Wd1 rows 0..127
        else {
            int p = k - 128;
            row = (p < 64) ? 192 + p                            // g_xt[0:64)  = ob_t  -> Wd1 rows 192..255
                : (p < 128) ? 128 + (p - 64)                    // g_xt[64:128)= ns    -> Wd1 rows 128..191
                : 256 + (p - 128);                              // g_xt[128:138)=ac_t  -> Wd1 rows 256..265
        }
        s_wd1[j][k] = Wd1[row*256 + j0 + j];
    }
    for (int e = tid; e < 256; e += NTH){ s_wmu[e] = Wmu[e*64 + o6]; s_wstd[e] = Wstd[e*64 + o6]; }
    if (tid < 2)                 s_b[tid]    = bt1[j0 + tid];
    else if (tid == 2)           s_b[2]      = bt2[o6];
    else if (tid >= 3  && tid < 6)  s_b[tid] = bih0[cta + (tid-3)*128];
    else if (tid >= 6  && tid < 9)  s_b[tid] = bhh0[cta + (tid-6)*128];
    else if (tid >= 9  && tid < 12) s_b[tid] = bih1[cta + (tid-9)*128];
    else if (tid >= 12 && tid < 15) s_b[tid] = bhh1[cta + (tid-12)*128];
    else if (tid >= 15 && tid < 17) s_b[tid] = bd1[j0 + tid - 15];
    else if (tid == 17)          s_b[17]     = bmu[o6];
    else if (tid == 18)          s_b[18]     = bstd[o6];
    s_seq[tid] = seql[tid];

    // ---- global state init (transposed to [k][b]) ----
    for (int e = gt; e < 128*B; e += GRID*NTH){
        int k = e >> 8, b = e & 255;
        g_h0[0][k][b] = prev[b*320 + k];
        g_h1[0][k][b] = prev[b*320 + 128 + k];
    }
    for (int e = gt; e < 64*B; e += GRID*NTH){
        int k = e >> 8, b = e & 255;
        g_obsim[k][b] = prev[b*320 + 256 + k];
    }
    for (int e = gt; e < 74*B; e += GRID*NTH){          // stage inputs for t=0
        int r = e >> 8, b = e & 255;
        float v = (r < 64) ? ob[((size_t)b*T)*64 + r] : acg[((size_t)b*T)*10 + (r - 64)];
        g_xt[(r < 64) ? r : 64 + r][b] = v;
    }

    __syncthreads();
    unsigned bar = s_base;
    grid_barrier(++bar);    // init done

    float* mus  = out;
    float* stds = out + (size_t)B*T*64;
    float* rets = out + (size_t)2*B*T*64;
    float* last = rets + (size_t)B*T*320;

    for (int t = 0; t < T; ++t){
        const int p = t & 1, pn = p ^ 1;

        // ---- S1: t1 = tanh([ob_sim, ac] @ Wt1 + bt1), 2 neurons per CTA, b = tid ----
        {
            const int b = tid;
            float a0 = s_b[0], a1 = s_b[1];
            #pragma unroll 4
            for (int k = 0; k < 64; ++k){ float a = g_obsim[k][b]; a0 += a*s_wt1[0][k]; a1 += a*s_wt1[1][k]; }
            #pragma unroll
            for (int q = 0; q < 10; ++q){ float a = g_xt[128+q][b]; a0 += a*s_wt1[0][64+q]; a1 += a*s_wt1[1][64+q]; }
            g_t1[j0][b]   = tanhf(a0);
            g_t1[j0+1][b] = tanhf(a1);
        }
        grid_barrier(++bar);

        // ---- S2: next_ob_sim = t1 @ Wt2 + bt2 (linear), 1 neuron / half-batch per CTA ----
        if (tid < 128){
            const int b = half*128 + tid;
            float a0 = s_b[2];
            #pragma unroll 4
            for (int k = 0; k < 256; ++k) a0 += g_t1[k][b] * s_wt2[k];
            g_xt[64 + o6][b] = a0;
        }
        grid_barrier(++bar);

        // ---- S3: GRU0, neuron i = cta, b = tid ----
        {
            const int b = tid;
            const float m = (t < s_seq[b]) ? 1.0f : 0.0f;
            float ir=0.f, iz=0.f, inn=0.f, hr=0.f, hz=0.f, hn=0.f;
            #pragma unroll 4
            for (int k = 0; k < 138; ++k){
                float a = g_xt[k][b];
                ir += a*s_wih0[0][k]; iz += a*s_wih0[1][k]; inn += a*s_wih0[2][k];
            }
            #pragma unroll 4
            for (int k = 0; k < 128; ++k){
                float a = g_h0[p][k][b];
                hr += a*s_whh0[0][k]; hz += a*s_whh0[1][k]; hn += a*s_whh0[2][k];
            }
            float r = sigmoidf_(ir + s_b[3] + hr + s_b[6]);
            float z = sigmoidf_(iz + s_b[4] + hz + s_b[7]);
            float n = tanhf(inn + s_b[5] + r*(hn + s_b[8]));
            float hp  = g_h0[p][cta][b];
            float nh0 = (1.0f - z)*n + z*hp;
            g_nh0[cta][b] = nh0;                      // raw, for GRU1
            float h0n = m * nh0;
            g_h0[pn][cta][b] = h0n;
            rets[((size_t)b*T + t)*320 + cta] = h0n;
            if (t == T-1) last[b*320 + cta] = h0n;
        }
        grid_barrier(++bar);

        // ---- S4: GRU1, neuron i = cta, b = tid ----
        {
            const int b = tid;
            const float m = (t < s_seq[b]) ? 1.0f : 0.0f;
            float ir=0.f, iz=0.f, inn=0.f, hr=0.f, hz=0.f, hn=0.f;
            #pragma unroll 4
            for (int k = 0; k < 128; ++k){
                float a = g_nh0[k][b];
                ir += a*s_wih1[0][k]; iz += a*s_wih1[1][k]; inn += a*s_wih1[2][k];
            }
            #pragma unroll 4
            for (int k = 0; k < 128; ++k){
                float a = g_h1[p][k][b];
                hr += a*s_whh1[0][k]; hz += a*s_whh1[1][k]; hn += a*s_whh1[2][k];
            }
            float r = sigmoidf_(ir + s_b[9]  + hr + s_b[12]);
            float z = sigmoidf_(iz + s_b[10] + hz + s_b[13]);
            float n = tanhf(inn + s_b[11] + r*(hn + s_b[14]));
            float hp  = g_h1[p][cta][b];
            float nh1 = (1.0f - z)*n + z*hp;
            float h1n = m * nh1;                      // == out AND new h1
            g_h1[pn][cta][b] = h1n;
            rets[((size_t)b*T + t)*320 + 128 + cta] = h1n;
            if (t == T-1) last[b*320 + 128 + cta] = h1n;
        }
        grid_barrier(++bar);

        // ---- S5: hdec = tanh([out, ns, ob, ac] @ Wd1 + bd1), 2 neurons per CTA ----
        {
            const int b = tid;
            float a0 = s_b[15], a1 = s_b[16];
            #pragma unroll 4
            for (int k = 0; k < 128; ++k){
                float a = g_h1[pn][k][b];
                a0 += a*s_wd1[0][k]; a1 += a*s_wd1[1][k];
            }
            #pragma unroll 4
            for (int k = 0; k < 138; ++k){
                float a = g_xt[k][b];
                a0 += a*s_wd1[0][128+k]; a1 += a*s_wd1[1][128+k];
            }
            g_hdec[j0][b]   = tanhf(a0);
            g_hdec[j0+1][b] = tanhf(a1);
        }
        grid_barrier(++bar);

        // ---- S6: mu/std/ob_sim + outputs; stage next step's inputs ----
        if (tid < 128){
            const int b = half*128 + tid;
            float mu = s_b[17], sd = s_b[18];
            #pragma unroll 4
            for (int k = 0; k < 256; ++k){
                float a = g_hdec[k][b];
                mu += a*s_wmu[k]; sd += a*s_wstd[k];
            }
            float sp   = (sd > 20.0f) ? sd : log1pf(expf(sd));
            float stdv = sp + 1e-4f;
            float eps  = noise[((size_t)b*T + t)*64 + o6];
            float os   = mu + stdv * eps;
            g_obsim[o6][b] = os;
            mus [((size_t)b*T + t)*64 + o6] = mu;
            stds[((size_t)b*T + t)*64 + o6] = stdv;
            rets[((size_t)b*T + t)*320 + 256 + o6] = os;
            if (t == T-1) last[b*320 + 256 + o6] = os;
        }
        if (t + 1 < T){
            for (int e = gt; e < 74*B; e += GRID*NTH){
                int r = e >> 8, b = e & 255;
                float v = (r < 64) ? ob[((size_t)b*T + (t+1))*64 + r]
                                   : acg[((size_t)b*T + (t+1))*10 + (r - 64)];
                g_xt[(r < 64) ? r : 64 + r][b] = v;
            }
        }
        grid_barrier(++bar);
    }
}

extern "C" void kernel_launch(void* const* d_in, const int* in_sizes, int n_in,
                              void* d_out, int out_size)
{
    (void)in_sizes; (void)n_in; (void)out_size;
    rnn_kernel<<<GRID, NTH>>>(
        (const float*)d_in[0],  (const float*)d_in[1],  (const float*)d_in[2],
        (const float*)d_in[3],  (const int*)  d_in[4],
        (const float*)d_in[5],  (const float*)d_in[6],  (const float*)d_in[7],  (const float*)d_in[8],
        (const float*)d_in[9],  (const float*)d_in[10], (const float*)d_in[11], (const float*)d_in[12],
        (const float*)d_in[13], (const float*)d_in[14], (const float*)d_in[15], (const float*)d_in[16],
        (const float*)d_in[17], (const float*)d_in[18],
        (const float*)d_in[19], (const float*)d_in[20], (const float*)d_in[21], (const float*)d_in[22],
        (float*)d_out);
}

// round 3
// speedup vs baseline: 2.2392x; 2.2392x over previous
#include <cuda_runtime.h>

#define GRID 128
#define NTH  512
#define B    256
#define T    512

// ---------------- persistent device state (allocation-free scratch) ----------
__device__ float g_obsim[64][B];        // ob_sim, [o][b]
__device__ float g_h0[2][128][B];       // double-buffered masked h0
__device__ float g_h1[2][128][B];       // double-buffered masked h1
__device__ float g_xt[138][B];          // x concat: [0:64)=ob_t, [64:128)=next_ob_sim, [128:138)=ac_t
__device__ float g_t1[256][B];          // transition hidden
__device__ float g_nh0[128][B];         // raw (unmasked) nh0 for GRU1 input
__device__ float g_hdec[256][B];        // decoder hidden
__device__ unsigned g_bar_count;        // monotonic across launches
__device__ unsigned g_bar_gen;          // monotonic across launches

__device__ __forceinline__ float sigmoidf_(float x){ return 1.0f/(1.0f + expf(-x)); }

__device__ __forceinline__ void grid_barrier(unsigned target){
    __syncthreads();
    if (threadIdx.x == 0){
        __threadfence();
        unsigned old = atomicAdd(&g_bar_count, 1u);
        if (old == target * GRID - 1u){
            asm volatile("st.release.gpu.u32 [%0], %1;" :: "l"(&g_bar_gen), "r"(target) : "memory");
        } else {
            unsigned v;
            do {
                asm volatile("ld.acquire.gpu.u32 %0, [%1];" : "=r"(v) : "l"(&g_bar_gen) : "memory");
            } while ((int)(v - target) < 0);
        }
    }
    __syncthreads();
}

__global__ void __launch_bounds__(NTH, 1) rnn_kernel(
    const float* __restrict__ ob,   const float* __restrict__ acg,  const float* __restrict__ noise,
    const float* __restrict__ prev, const int*   __restrict__ seql,
    const float* __restrict__ Wih0, const float* __restrict__ Whh0, const float* __restrict__ bih0, const float* __restrict__ bhh0,
    const float* __restrict__ Wih1, const float* __restrict__ Whh1, const float* __restrict__ bih1, const float* __restrict__ bhh1,
    const float* __restrict__ Wt1,  const float* __restrict__ bt1,  const float* __restrict__ Wt2,  const float* __restrict__ bt2,
    const float* __restrict__ Wd1,  const float* __restrict__ bd1,
    const float* __restrict__ Wmu,  const float* __restrict__ bmu,  const float* __restrict__ Wstd, const float* __restrict__ bstd,
    float* __restrict__ out)
{
    const int cta = blockIdx.x;
    const int tid = threadIdx.x;
    const int gt  = cta * NTH + tid;

    // ---- per-CTA static weight slices in SMEM ----
    __shared__ float s_wt1[2][74];          // trans1 cols (j0, j0+1)
    __shared__ float s_wt2[256];            // trans2 col o6
    __shared__ float s_wih0[3][138];        // GRU0 rows i, i+128, i+256
    __shared__ float s_whh0[3][128];
    __shared__ float s_wih1[3][128];        // GRU1
    __shared__ float s_whh1[3][128];
    __shared__ float s_wd1[2][266];         // dec1 cols (j0, j0+1), rows reordered to [h1 | g_xt order]
    __shared__ float s_wmu[256], s_wstd[256];
    __shared__ float s_b[20];
    __shared__ int   s_seq[B];
    __shared__ unsigned s_base;
    __shared__ float s_red[3][256];         // cross-group partial-sum buffer

    const int j0   = 2 * cta;               // S1/S5 neuron pair
    const int o6   = cta >> 1;              // S2/S6 neuron
    const int half = cta & 1;               // batch half for S2/S6

    if (tid == 0) s_base = *((volatile unsigned*)&g_bar_gen);

    for (int e = tid; e < 2*74; e += NTH){ int j=e/74, k=e%74; s_wt1[j][k] = Wt1[k*256 + j0 + j]; }
    for (int e = tid; e < 256;  e += NTH) s_wt2[e] = Wt2[e*64 + o6];
    for (int e = tid; e < 3*138; e += NTH){ int g=e/138, k=e%138; s_wih0[g][k] = Wih0[(cta + g*128)*138 + k]; }
    for (int e = tid; e < 3*128; e += NTH){
        int g=e/128, k=e%128;
        s_whh0[g][k] = Whh0[(cta + g*128)*128 + k];
        s_wih1[g][k] = Wih1[(cta + g*128)*128 + k];
        s_whh1[g][k] = Whh1[(cta + g*128)*128 + k];
    }
    for (int e = tid; e < 2*266; e += NTH){
        int j=e/266, k=e%266, row;
        if (k < 128) row = k;                                   // h1 (out) part: Wd1 rows 0..127
        else {
            int p = k - 128;
            row = (p < 64) ? 192 + p                            // g_xt[0:64)  = ob_t  -> Wd1 rows 192..255
                : (p < 128) ? 128 + (p - 64)                    // g_xt[64:128)= ns    -> Wd1 rows 128..191
                : 256 + (p - 128);                              // g_xt[128:138)=ac_t  -> Wd1 rows 256..265
        }
        s_wd1[j][k] = Wd1[row*256 + j0 + j];
    }
    for (int e = tid; e < 256; e += NTH){ s_wmu[e] = Wmu[e*64 + o6]; s_wstd[e] = Wstd[e*64 + o6]; }
    if (tid < 2)                 s_b[tid]    = bt1[j0 + tid];
    else if (tid == 2)           s_b[2]      = bt2[o6];
    else if (tid >= 3  && tid < 6)  s_b[tid] = bih0[cta + (tid-3)*128];
    else if (tid >= 6  && tid < 9)  s_b[tid] = bhh0[cta + (tid-6)*128];
    else if (tid >= 9  && tid < 12) s_b[tid] = bih1[cta + (tid-9)*128];
    else if (tid >= 12 && tid < 15) s_b[tid] = bhh1[cta + (tid-12)*128];
    else if (tid >= 15 && tid < 17) s_b[tid] = bd1[j0 + tid - 15];
    else if (tid == 17)          s_b[17]     = bmu[o6];
    else if (tid == 18)          s_b[18]     = bstd[o6];
    if (tid < B) s_seq[tid] = seql[tid];

    // ---- global state init (transposed to [k][b]) ----
    for (int e = gt; e < 128*B; e += GRID*NTH){
        int k = e >> 8, b = e & 255;
        g_h0[0][k][b] = prev[b*320 + k];
        g_h1[0][k][b] = prev[b*320 + 128 + k];
    }
    for (int e = gt; e < 64*B; e += GRID*NTH){
        int k = e >> 8, b = e & 255;
        g_obsim[k][b] = prev[b*320 + 256 + k];
    }
    for (int e = gt; e < 74*B; e += GRID*NTH){          // stage inputs for t=0
        int r = e >> 8, b = e & 255;
        float v = (r < 64) ? ob[((size_t)b*T)*64 + r] : acg[((size_t)b*T)*10 + (r - 64)];
        g_xt[(r < 64) ? r : 64 + r][b] = v;
    }

    __syncthreads();
    unsigned bar = s_base;
    grid_barrier(++bar);    // init done

    float* mus  = out;
    float* stds = out + (size_t)B*T*64;
    float* rets = out + (size_t)2*B*T*64;
    float* last = rets + (size_t)B*T*320;

    const int b8 = tid & 255;     // batch for full-batch stages
    const int g8 = tid >> 8;      // 0/1 group
    const int b7 = tid & 127;     // batch-within-half for S2/S6
    const int g7 = tid >> 7;      // 0..3 group
    const int bS26 = half*128 + b7;

    for (int t = 0; t < T; ++t){
        const int p = t & 1, pn = p ^ 1;

        // ---- S1: t1 = tanh([ob_sim, ac] @ Wt1 + bt1); neuron j0+g8, b = b8 ----
        {
            float a0 = s_b[g8];
            #pragma unroll 8
            for (int k = 0; k < 64; ++k) a0 += g_obsim[k][b8] * s_wt1[g8][k];
            #pragma unroll
            for (int q = 0; q < 10; ++q) a0 += g_xt[128+q][b8] * s_wt1[g8][64+q];
            g_t1[j0+g8][b8] = tanhf(a0);
        }
        grid_barrier(++bar);

        // ---- S2: next_ob_sim = t1 @ Wt2 + bt2; neuron o6, K split 4-ways ----
        {
            const int kb = g7 * 64;
            float a0 = 0.f;
            #pragma unroll 8
            for (int k = 0; k < 64; ++k) a0 += g_t1[kb+k][bS26] * s_wt2[kb+k];
            if (g7) s_red[g7-1][b7] = a0;
            __syncthreads();
            if (!g7) g_xt[64 + o6][bS26] = a0 + s_red[0][b7] + s_red[1][b7] + s_red[2][b7] + s_b[2];
        }
        grid_barrier(++bar);

        // ---- S3: GRU0, neuron i = cta; group0 = x-gates, group1 = h-gates ----
        {
            float ir=0.f, iz=0.f, inn=0.f, hp=0.f;
            if (g8){
                float hr=0.f, hz=0.f, hn=0.f;
                #pragma unroll 8
                for (int k = 0; k < 128; ++k){
                    float a = g_h0[p][k][b8];
                    hr += a*s_whh0[0][k]; hz += a*s_whh0[1][k]; hn += a*s_whh0[2][k];
                }
                s_red[0][b8] = hr + s_b[6];
                s_red[1][b8] = hz + s_b[7];
                s_red[2][b8] = hn + s_b[8];
            } else {
                hp = g_h0[p][cta][b8];
                #pragma unroll 8
                for (int k = 0; k < 138; ++k){
                    float a = g_xt[k][b8];
                    ir += a*s_wih0[0][k]; iz += a*s_wih0[1][k]; inn += a*s_wih0[2][k];
                }
            }
            __syncthreads();
            if (!g8){
                const float m = (t < s_seq[b8]) ? 1.0f : 0.0f;
                float r = sigmoidf_(ir + s_b[3] + s_red[0][b8]);
                float z = sigmoidf_(iz + s_b[4] + s_red[1][b8]);
                float n = tanhf(inn + s_b[5] + r * s_red[2][b8]);
                float nh0 = (1.0f - z)*n + z*hp;
                g_nh0[cta][b8] = nh0;
                float h0n = m * nh0;
                g_h0[pn][cta][b8] = h0n;
                rets[((size_t)b8*T + t)*320 + cta] = h0n;
                if (t == T-1) last[b8*320 + cta] = h0n;
            }
        }
        grid_barrier(++bar);

        // ---- S4: GRU1, neuron i = cta; group0 = x-gates (from nh0), group1 = h-gates ----
        {
            float ir=0.f, iz=0.f, inn=0.f, hp=0.f;
            if (g8){
                float hr=0.f, hz=0.f, hn=0.f;
                #pragma unroll 8
                for (int k = 0; k < 128; ++k){
                    float a = g_h1[p][k][b8];
                    hr += a*s_whh1[0][k]; hz += a*s_whh1[1][k]; hn += a*s_whh1[2][k];
                }
                s_red[0][b8] = hr + s_b[12];
                s_red[1][b8] = hz + s_b[13];
                s_red[2][b8] = hn + s_b[14];
            } else {
                hp = g_h1[p][cta][b8];
                #pragma unroll 8
                for (int k = 0; k < 128; ++k){
                    float a = g_nh0[k][b8];
                    ir += a*s_wih1[0][k]; iz += a*s_wih1[1][k]; inn += a*s_wih1[2][k];
                }
            }
            __syncthreads();
            if (!g8){
                const float m = (t < s_seq[b8]) ? 1.0f : 0.0f;
                float r = sigmoidf_(ir + s_b[9]  + s_red[0][b8]);
                float z = sigmoidf_(iz + s_b[10] + s_red[1][b8]);
                float n = tanhf(inn + s_b[11] + r * s_red[2][b8]);
                float nh1 = (1.0f - z)*n + z*hp;
                float h1n = m * nh1;
                g_h1[pn][cta][b8] = h1n;
                rets[((size_t)b8*T + t)*320 + 128 + cta] = h1n;
                if (t == T-1) last[b8*320 + 128 + cta] = h1n;
            }
        }
        grid_barrier(++bar);

        // ---- S5: hdec = tanh([out, ns, ob, ac] @ Wd1 + bd1); neuron j0+g8 ----
        {
            float a0 = s_b[15 + g8];
            #pragma unroll 8
            for (int k = 0; k < 128; ++k) a0 += g_h1[pn][k][b8] * s_wd1[g8][k];
            #pragma unroll 8
            for (int k = 0; k < 138; ++k) a0 += g_xt[k][b8] * s_wd1[g8][128+k];
            g_hdec[j0+g8][b8] = tanhf(a0);
        }
        grid_barrier(++bar);

        // ---- S6: mu/std/ob_sim + outputs; K split 4-ways, both outputs per group ----
        {
            const int kb = g7 * 64;
            float mu = 0.f, sd = 0.f;
            #pragma unroll 8
            for (int k = 0; k < 64; ++k){
                float a = g_hdec[kb+k][bS26];
                mu += a*s_wmu[kb+k]; sd += a*s_wstd[kb+k];
            }
            if (g7){ s_red[g7-1][b7] = mu; s_red[g7-1][128 + b7] = sd; }
            __syncthreads();
            if (!g7){
                mu += s_red[0][b7] + s_red[1][b7] + s_red[2][b7] + s_b[17];
                sd += s_red[0][128+b7] + s_red[1][128+b7] + s_red[2][128+b7] + s_b[18];
                float sp   = (sd > 20.0f) ? sd : log1pf(expf(sd));
                float stdv = sp + 1e-4f;
                float eps  = noise[((size_t)bS26*T + t)*64 + o6];
                float os   = mu + stdv * eps;
                g_obsim[o6][bS26] = os;
                mus [((size_t)bS26*T + t)*64 + o6] = mu;
                stds[((size_t)bS26*T + t)*64 + o6] = stdv;
                rets[((size_t)bS26*T + t)*320 + 256 + o6] = os;
                if (t == T-1) last[bS26*320 + 256 + o6] = os;
            }
            if (t + 1 < T){
                for (int e = gt; e < 74*B; e += GRID*NTH){
                    int r = e >> 8, b = e & 255;
                    float v = (r < 64) ? ob[((size_t)b*T + (t+1))*64 + r]
                                       : acg[((size_t)b*T + (t+1))*10 + (r - 64)];
                    g_xt[(r < 64) ? r : 64 + r][b] = v;
                }
            }
        }
        grid_barrier(++bar);
    }
}

extern "C" void kernel_launch(void* const* d_in, const int* in_sizes, int n_in,
                              void* d_out, int out_size)
{
    (void)in_sizes; (void)n_in; (void)out_size;
    rnn_kernel<<<GRID, NTH>>>(
        (const float*)d_in[0],  (const float*)d_in[1],  (const float*)d_in[2],
        (const float*)d_in[3],  (const int*)  d_in[4],
        (const float*)d_in[5],  (const float*)d_in[6],  (const float*)d_in[7],  (const float*)d_in[8],
        (const float*)d_in[9],  (const float*)d_in[10], (const float*)d_in[11], (const float*)d_in[12],
        (const float*)d_in[13], (const float*)d_in[14], (const float*)d_in[15], (const float*)d_in[16],
        (const float*)d_in[17], (const float*)d_in[18],
        (const float*)d_in[19], (const float*)d_in[20], (const float*)d_in[21], (const float*)d_in[22],
        (float*)d_out);
}

// round 8
// speedup vs baseline: 3.4703x; 1.5498x over previous
#include <cuda_runtime.h>

#define GRID 128
#define NTH  512
#define B    256
#define T    512

// ---------------- persistent device state (float4 over batch: [K][B/4]) ----
__device__ float4 g_obsim[64][64];
__device__ float4 g_h0[2][128][64];
__device__ float4 g_h1[2][128][64];
__device__ float4 g_xt[138][64];     // [0:64)=ob_t, [64:128)=next_ob_sim, [128:138)=ac_t
__device__ float4 g_t1[256][64];
__device__ float4 g_nh0[128][64];
__device__ float4 g_hdec[256][64];
__device__ unsigned g_bar_count;
__device__ unsigned g_bar_gen;

__device__ __forceinline__ float sigmoidf_(float x){ return 1.0f/(1.0f + expf(-x)); }
__device__ __forceinline__ void fma4(float4& a, const float4 v, const float w){
    a.x += v.x*w; a.y += v.y*w; a.z += v.z*w; a.w += v.w*w;
}

__device__ __forceinline__ void grid_barrier(unsigned target){
    __syncthreads();
    if (threadIdx.x == 0){
        __threadfence();
        unsigned old = atomicAdd(&g_bar_count, 1u);
        if (old == target * GRID - 1u){
            asm volatile("st.release.gpu.u32 [%0], %1;" :: "l"(&g_bar_gen), "r"(target) : "memory");
        } else {
            unsigned v;
            do {
                asm volatile("ld.acquire.gpu.u32 %0, [%1];" : "=r"(v) : "l"(&g_bar_gen) : "memory");
            } while ((int)(v - target) < 0);
        }
    }
    __syncthreads();
}

__global__ void __launch_bounds__(NTH, 1) rnn_kernel(
    const float* __restrict__ ob,   const float* __restrict__ acg,  const float* __restrict__ noise,
    const float* __restrict__ prev, const int*   __restrict__ seql,
    const float* __restrict__ Wih0, const float* __restrict__ Whh0, const float* __restrict__ bih0, const float* __restrict__ bhh0,
    const float* __restrict__ Wih1, const float* __restrict__ Whh1, const float* __restrict__ bih1, const float* __restrict__ bhh1,
    const float* __restrict__ Wt1,  const float* __restrict__ bt1,  const float* __restrict__ Wt2,  const float* __restrict__ bt2,
    const float* __restrict__ Wd1,  const float* __restrict__ bd1,
    const float* __restrict__ Wmu,  const float* __restrict__ bmu,  const float* __restrict__ Wstd, const float* __restrict__ bstd,
    float* __restrict__ out)
{
    const int cta = blockIdx.x;
    const int tid = threadIdx.x;
    const int gt  = cta * NTH + tid;

    // ---- per-CTA static weight slices in SMEM ----
    __shared__ float s_wt1[2][74];
    __shared__ float s_wt2[256];
    __shared__ float s_wih0[3][138];
    __shared__ float s_whh0[3][128];
    __shared__ float s_wih1[3][128];
    __shared__ float s_whh1[3][128];
    __shared__ float s_wd1[2][266];          // cols (j0,j0+1), rows reordered [h1 | g_xt order]
    __shared__ float s_wmu[256], s_wstd[256];
    __shared__ float s_b[20];
    __shared__ int   s_seq[B];
    __shared__ unsigned s_base;
    __shared__ float4 s_part[1536];          // chunk partial sums (24.5 KB)

    const int j0   = 2 * cta;
    const int o6   = cta >> 1;
    const int half = cta & 1;

    if (tid == 0) s_base = *((volatile unsigned*)&g_bar_gen);

    for (int e = tid; e < 2*74; e += NTH){ int j=e/74, k=e%74; s_wt1[j][k] = Wt1[k*256 + j0 + j]; }
    for (int e = tid; e < 256;  e += NTH) s_wt2[e] = Wt2[e*64 + o6];
    for (int e = tid; e < 3*138; e += NTH){ int g=e/138, k=e%138; s_wih0[g][k] = Wih0[(cta + g*128)*138 + k]; }
    for (int e = tid; e < 3*128; e += NTH){
        int g=e/128, k=e%128;
        s_whh0[g][k] = Whh0[(cta + g*128)*128 + k];
        s_wih1[g][k] = Wih1[(cta + g*128)*128 + k];
        s_whh1[g][k] = Whh1[(cta + g*128)*128 + k];
    }
    for (int e = tid; e < 2*266; e += NTH){
        int j=e/266, k=e%266, row;
        if (k < 128) row = k;
        else {
            int pp = k - 128;
            row = (pp < 64) ? 192 + pp
                : (pp < 128) ? 128 + (pp - 64)
                : 256 + (pp - 128);
        }
        s_wd1[j][k] = Wd1[row*256 + j0 + j];
    }
    for (int e = tid; e < 256; e += NTH){ s_wmu[e] = Wmu[e*64 + o6]; s_wstd[e] = Wstd[e*64 + o6]; }
    if (tid < 2)                 s_b[tid]    = bt1[j0 + tid];
    else if (tid == 2)           s_b[2]      = bt2[o6];
    else if (tid >= 3  && tid < 6)  s_b[tid] = bih0[cta + (tid-3)*128];
    else if (tid >= 6  && tid < 9)  s_b[tid] = bhh0[cta + (tid-6)*128];
    else if (tid >= 9  && tid < 12) s_b[tid] = bih1[cta + (tid-9)*128];
    else if (tid >= 12 && tid < 15) s_b[tid] = bhh1[cta + (tid-12)*128];
    else if (tid >= 15 && tid < 17) s_b[tid] = bd1[j0 + tid - 15];
    else if (tid == 17)          s_b[17]     = bmu[o6];
    else if (tid == 18)          s_b[18]     = bstd[o6];
    if (tid < B) s_seq[tid] = seql[tid];

    // ---- global state init (chip-partitioned; scalar aliases of float4 arrays) ----
    for (int e = gt; e < 128*B; e += GRID*NTH){
        int k = e >> 8, b = e & 255;
        ((float*)&g_h0[0][k][0])[b] = prev[b*320 + k];
        ((float*)&g_h1[0][k][0])[b] = prev[b*320 + 128 + k];
    }
    for (int e = gt; e < 64*B; e += GRID*NTH){
        int k = e >> 8, b = e & 255;
        ((float*)&g_obsim[k][0])[b] = prev[b*320 + 256 + k];
    }
    for (int e = gt; e < 74*B; e += GRID*NTH){
        int r = e >> 8, b = e & 255;
        float v = (r < 64) ? ob[((size_t)b*T)*64 + r] : acg[((size_t)b*T)*10 + (r - 64)];
        ((float*)&g_xt[(r < 64) ? r : 64 + r][0])[b] = v;
    }

    __syncthreads();
    unsigned bar = s_base;
    grid_barrier(++bar);

    float* mus  = out;
    float* stds = out + (size_t)B*T*64;
    float* rets = out + (size_t)2*B*T*64;
    float* last = rets + (size_t)B*T*320;

    const int bq  = tid & 63;      // batch quad (full-B stages)
    const int sg  = tid >> 6;      // 0..7
    const int tq  = tid & 31;      // batch quad within half (S2/S6)
    const int s16 = tid >> 5;      // 0..15

    const float4 z4 = {0.f,0.f,0.f,0.f};

    for (int t = 0; t < T; ++t){
        const int p = t & 1, pn = p ^ 1;

        // ---- S1: t1 = tanh([ob_sim, ac] @ Wt1 + bt1); both neurons, 8 k-chunks ----
        {
            const int ks = (74*sg) >> 3, ke = (74*(sg+1)) >> 3;
            float4 a0 = z4, a1 = z4;
            const int k1 = (ke < 64) ? ke : 64;
            #pragma unroll 4
            for (int k = ks; k < k1; ++k){
                float4 v = g_obsim[k][bq];
                fma4(a0, v, s_wt1[0][k]); fma4(a1, v, s_wt1[1][k]);
            }
            const int k2 = (ks > 64) ? ks : 64;
            #pragma unroll 4
            for (int k = k2; k < ke; ++k){
                float4 v = g_xt[64 + k][bq];         // row 128+(k-64)
                fma4(a0, v, s_wt1[0][k]); fma4(a1, v, s_wt1[1][k]);
            }
            s_part[sg*64 + bq] = a0;
            s_part[512 + sg*64 + bq] = a1;
            __syncthreads();
            if (tid < 128){
                int nr = tid >> 6, q = tid & 63;
                float4 s = s_part[nr*512 + q];
                #pragma unroll
                for (int c = 1; c < 8; ++c){
                    float4 pzz = s_part[nr*512 + c*64 + q];
                    s.x += pzz.x; s.y += pzz.y; s.z += pzz.z; s.w += pzz.w;
                }
                float bb = s_b[nr];
                float4 r;
                r.x = tanhf(s.x + bb); r.y = tanhf(s.y + bb);
                r.z = tanhf(s.z + bb); r.w = tanhf(s.w + bb);
                g_t1[j0 + nr][q] = r;
            }
        }
        grid_barrier(++bar);

        // ---- S2: ns = t1 @ Wt2 + bt2; neuron o6, half batch, 16 k-chunks ----
        {
            const int ks = s16 * 16;
            float4 a = z4;
            #pragma unroll
            for (int k = 0; k < 16; ++k)
                fma4(a, g_t1[ks + k][half*32 + tq], s_wt2[ks + k]);
            s_part[s16*32 + tq] = a;
            __syncthreads();
            if (tid < 32){
                float4 s = s_part[tid];
                #pragma unroll
                for (int c = 1; c < 16; ++c){
                    float4 pzz = s_part[c*32 + tid];
                    s.x += pzz.x; s.y += pzz.y; s.z += pzz.z; s.w += pzz.w;
                }
                float bb = s_b[2];
                s.x += bb; s.y += bb; s.z += bb; s.w += bb;
                g_xt[64 + o6][half*32 + tid] = s;
            }
        }
        grid_barrier(++bar);

        // ---- S3: GRU0, neuron cta; sg0-3: x-gates, sg4-7: h-gates ----
        {
            if (sg < 4){
                const int ks = (138*sg) >> 2, ke = (138*(sg+1)) >> 2;
                float4 ar = z4, az = z4, an = z4;
                #pragma unroll 4
                for (int k = ks; k < ke; ++k){
                    float4 v = g_xt[k][bq];
                    fma4(ar, v, s_wih0[0][k]); fma4(az, v, s_wih0[1][k]); fma4(an, v, s_wih0[2][k]);
                }
                s_part[(0*4 + sg)*64 + bq] = ar;
                s_part[(1*4 + sg)*64 + bq] = az;
                s_part[(2*4 + sg)*64 + bq] = an;
            } else {
                const int c = sg - 4, ks = c*32;
                float4 ar = z4, az = z4, an = z4;
                #pragma unroll 4
                for (int k = ks; k < ks + 32; ++k){
                    float4 v = g_h0[p][k][bq];
                    fma4(ar, v, s_whh0[0][k]); fma4(az, v, s_whh0[1][k]); fma4(an, v, s_whh0[2][k]);
                }
                s_part[(3*4 + c)*64 + bq] = ar;
                s_part[(4*4 + c)*64 + bq] = az;
                s_part[(5*4 + c)*64 + bq] = an;
            }
            __syncthreads();
            if (tid < 256){
                const int b = tid, q = b >> 2, l = b & 3;
                const float* sp = (const float*)s_part;
                float ir=0.f, iz=0.f, inn=0.f, hr=0.f, hz=0.f, hn=0.f;
                #pragma unroll
                for (int c = 0; c < 4; ++c){
                    ir  += sp[((0*4+c)*64 + q)*4 + l];
                    iz  += sp[((1*4+c)*64 + q)*4 + l];
                    inn += sp[((2*4+c)*64 + q)*4 + l];
                    hr  += sp[((3*4+c)*64 + q)*4 + l];
                    hz  += sp[((4*4+c)*64 + q)*4 + l];
                    hn  += sp[((5*4+c)*64 + q)*4 + l];
                }
                const float m = (t < s_seq[b]) ? 1.0f : 0.0f;
                float r = sigmoidf_(ir + s_b[3] + hr + s_b[6]);
                float z = sigmoidf_(iz + s_b[4] + hz + s_b[7]);
                float n = tanhf(inn + s_b[5] + r*(hn + s_b[8]));
                float hp  = ((const float*)&g_h0[p][cta][0])[b];
                float nh0 = (1.0f - z)*n + z*hp;
                ((float*)&g_nh0[cta][0])[b] = nh0;
                float h0n = m * nh0;
                ((float*)&g_h0[pn][cta][0])[b] = h0n;
                rets[((size_t)b*T + t)*320 + cta] = h0n;
                if (t == T-1) last[b*320 + cta] = h0n;
            }
        }
        grid_barrier(++bar);

        // ---- S4: GRU1, neuron cta; sg0-3: x-gates (nh0), sg4-7: h-gates ----
        {
            if (sg < 4){
                const int ks = sg*32;
                float4 ar = z4, az = z4, an = z4;
                #pragma unroll 4
                for (int k = ks; k < ks + 32; ++k){
                    float4 v = g_nh0[k][bq];
                    fma4(ar, v, s_wih1[0][k]); fma4(az, v, s_wih1[1][k]); fma4(an, v, s_wih1[2][k]);
                }
                s_part[(0*4 + sg)*64 + bq] = ar;
                s_part[(1*4 + sg)*64 + bq] = az;
                s_part[(2*4 + sg)*64 + bq] = an;
            } else {
                const int c = sg - 4, ks = c*32;
                float4 ar = z4, az = z4, an = z4;
                #pragma unroll 4
                for (int k = ks; k < ks + 32; ++k){
                    float4 v = g_h1[p][k][bq];
                    fma4(ar, v, s_whh1[0][k]); fma4(az, v, s_whh1[1][k]); fma4(an, v, s_whh1[2][k]);
                }
                s_part[(3*4 + c)*64 + bq] = ar;
                s_part[(4*4 + c)*64 + bq] = az;
                s_part[(5*4 + c)*64 + bq] = an;
            }
            __syncthreads();
            if (tid < 256){
                const int b = tid, q = b >> 2, l = b & 3;
                const float* sp = (const float*)s_part;
                float ir=0.f, iz=0.f, inn=0.f, hr=0.f, hz=0.f, hn=0.f;
                #pragma unroll
                for (int c = 0; c < 4; ++c){
                    ir  += sp[((0*4+c)*64 + q)*4 + l];
                    iz  += sp[((1*4+c)*64 + q)*4 + l];
                    inn += sp[((2*4+c)*64 + q)*4 + l];
                    hr  += sp[((3*4+c)*64 + q)*4 + l];
                    hz  += sp[((4*4+c)*64 + q)*4 + l];
                    hn  += sp[((5*4+c)*64 + q)*4 + l];
                }
                const float m = (t < s_seq[b]) ? 1.0f : 0.0f;
                float r = sigmoidf_(ir + s_b[9]  + hr + s_b[12]);
                float z = sigmoidf_(iz + s_b[10] + hz + s_b[13]);
                float n = tanhf(inn + s_b[11] + r*(hn + s_b[14]));
                float hp  = ((const float*)&g_h1[p][cta][0])[b];
                float nh1 = (1.0f - z)*n + z*hp;
                float h1n = m * nh1;
                ((float*)&g_h1[pn][cta][0])[b] = h1n;
                rets[((size_t)b*T + t)*320 + 128 + cta] = h1n;
                if (t == T-1) last[b*320 + 128 + cta] = h1n;
            }
        }
        grid_barrier(++bar);

        // ---- S5: hdec = tanh([out | xt-order] @ wd1); both neurons, 8 k-chunks ----
        {
            const int ks = (266*sg) >> 3, ke = (266*(sg+1)) >> 3;
            float4 a0 = z4, a1 = z4;
            const int k1 = (ke < 128) ? ke : 128;
            #pragma unroll 4
            for (int k = ks; k < k1; ++k){
                float4 v = g_h1[pn][k][bq];
                fma4(a0, v, s_wd1[0][k]); fma4(a1, v, s_wd1[1][k]);
            }
            const int k2 = (ks > 128) ? ks : 128;
            #pragma unroll 4
            for (int k = k2; k < ke; ++k){
                float4 v = g_xt[k - 128][bq];
                fma4(a0, v, s_wd1[0][k]); fma4(a1, v, s_wd1[1][k]);
            }
            s_part[sg*64 + bq] = a0;
            s_part[512 + sg*64 + bq] = a1;
            __syncthreads();
            if (tid < 128){
                int nr = tid >> 6, q = tid & 63;
                float4 s = s_part[nr*512 + q];
                #pragma unroll
                for (int c = 1; c < 8; ++c){
                    float4 pzz = s_part[nr*512 + c*64 + q];
                    s.x += pzz.x; s.y += pzz.y; s.z += pzz.z; s.w += pzz.w;
                }
                float bb = s_b[15 + nr];
                float4 r;
                r.x = tanhf(s.x + bb); r.y = tanhf(s.y + bb);
                r.z = tanhf(s.z + bb); r.w = tanhf(s.w + bb);
                g_hdec[j0 + nr][q] = r;
            }
        }
        grid_barrier(++bar);

        // ---- S6: mu/std/ob_sim; neuron o6, half batch, 16 k-chunks, both outputs ----
        {
            const int ks = s16 * 16;
            float4 am = z4, av = z4;
            #pragma unroll
            for (int k = 0; k < 16; ++k){
                float4 v = g_hdec[ks + k][half*32 + tq];
                fma4(am, v, s_wmu[ks + k]); fma4(av, v, s_wstd[ks + k]);
            }
            s_part[s16*32 + tq] = am;
            s_part[512 + s16*32 + tq] = av;
            __syncthreads();
            if (tid < 128){
                const int bh = tid, q = bh >> 2, l = bh & 3;
                const int b = half*128 + bh;
                const float* sp = (const float*)s_part;
                float mu = s_b[17], sd = s_b[18];
                #pragma unroll
                for (int c = 0; c < 16; ++c){
                    mu += sp[(c*32 + q)*4 + l];
                    sd += sp[(512 + c*32 + q)*4 + l];
                }
                float sp_  = (sd > 20.0f) ? sd : log1pf(expf(sd));
                float stdv = sp_ + 1e-4f;
                float eps  = noise[((size_t)b*T + t)*64 + o6];
                float os   = mu + stdv * eps;
                ((float*)&g_obsim[o6][0])[b] = os;
                mus [((size_t)b*T + t)*64 + o6] = mu;
                stds[((size_t)b*T + t)*64 + o6] = stdv;
                rets[((size_t)b*T + t)*320 + 256 + o6] = os;
                if (t == T-1) last[b*320 + 256 + o6] = os;
            }
            if (t + 1 < T){
                for (int e = gt; e < 74*B; e += GRID*NTH){
                    int r = e >> 8, b = e & 255;
                    float v = (r < 64) ? ob[((size_t)b*T + (t+1))*64 + r]
                                       : acg[((size_t)b*T + (t+1))*10 + (r - 64)];
                    ((float*)&g_xt[(r < 64) ? r : 64 + r][0])[b] = v;
                }
            }
        }
        grid_barrier(++bar);
    }
}

extern "C" void kernel_launch(void* const* d_in, const int* in_sizes, int n_in,
                              void* d_out, int out_size)
{
    (void)in_sizes; (void)n_in; (void)out_size;
    rnn_kernel<<<GRID, NTH>>>(
        (const float*)d_in[0],  (const float*)d_in[1],  (const float*)d_in[2],
        (const float*)d_in[3],  (const int*)  d_in[4],
        (const float*)d_in[5],  (const float*)d_in[6],  (const float*)d_in[7],  (const float*)d_in[8],
        (const float*)d_in[9],  (const float*)d_in[10], (const float*)d_in[11], (const float*)d_in[12],
        (const float*)d_in[13], (const float*)d_in[14], (const float*)d_in[15], (const float*)d_in[16],
        (const float*)d_in[17], (const float*)d_in[18],
        (const float*)d_in[19], (const float*)d_in[20], (const float*)d_in[21], (const float*)d_in[22],
        (float*)d_out);
}